// round 11
// baseline (speedup 1.0000x reference)
#include <cuda_runtime.h>
#include <cuda_bf16.h>

// Problem constants (reference: NUM_CLASSES=5532, F=256, Q=2*NUM_CLASSES, N=131072)
#define NC    5532
#define FEAT  256
#define NV4   (FEAT / 4)     // 64 float4 per row
#define RCAP  32             // per-replica bucket capacity (Poisson(~6)/replica)
#define CAP   (4 * RCAP)     // 128 rows per class
#define COPYB 512            // copy blocks leading the mean grid

// Scratch (device globals; zero-initialized at load, self-resetting per call)
__device__ int4     g_cnt4[NC];          // striped per-class counts (4 replicas)
__device__ int      g_pos[NC];           // final queue row for present classes
__device__ int      g_bucket[NC * CAP];  // row indices: [class][replica][slot]
__device__ int      g_wstart;            // circular write-window start
__device__ int      g_wlen;              // window length (#present classes)
__device__ unsigned g_done;              // block arrival counter (self-reset)

// ---------------------------------------------------------------------------
// 1) Bucket + scan in ONE kernel. All blocks ticket their labels (striped
//    replica = i&3); the LAST block to arrive (threadfence + counter) runs
//    the presence scan with its 256 threads: rank among present classes ->
//    circular queue position, plus the write window for the skip-copy.
// ---------------------------------------------------------------------------
__global__ void bucket_scan_kernel(const int* __restrict__ labels, int N,
                                   const int* __restrict__ tail_p, int Q) {
    int i = blockIdx.x * blockDim.x + threadIdx.x;
    if (i < N) {
        int c = labels[i];
        if (c >= 0 && c < NC) {
            int r = i & 3;
            int s = atomicAdd(&((int*)g_cnt4)[c * 4 + r], 1);
            if (s < RCAP) g_bucket[c * CAP + r * RCAP + s] = i;
        }
    }

    // ---- last-block election ----
    __syncthreads();
    __threadfence();                       // release our tickets
    __shared__ unsigned s_rank;
    if (threadIdx.x == 0) s_rank = atomicAdd(&g_done, 1u);
    __syncthreads();
    if (s_rank != gridDim.x - 1) return;
    __threadfence();                       // acquire everyone's tickets

    // ---- scan (256 threads, CHUNK classes each) ----
    const int T = 256;
    const int CHUNK = (NC + T - 1) / T;    // 22 (fits a 32-bit presence mask)
    int t    = threadIdx.x;
    int lane = t & 31;
    int warp = t >> 5;
    int base = t * CHUNK;

    unsigned mask = 0;
    int lp = 0;
#pragma unroll
    for (int k = 0; k < CHUNK; k++) {
        int c = base + k;
        if (c < NC) {
            int4 cv = __ldcg(&g_cnt4[c]);  // L2-level read (skip stale L1)
            if ((cv.x | cv.y | cv.z | cv.w) != 0) { mask |= 1u << k; lp++; }
        }
    }

    // warp-level inclusive scan of lp, then serial scan of 8 warp sums
    int ip = lp;
#pragma unroll
    for (int off = 1; off < 32; off <<= 1) {
        int v = __shfl_up_sync(0xffffffffu, ip, off);
        if (lane >= off) ip += v;
    }
    __shared__ int s_wsum[8];
    __shared__ int s_woff[8];
    __shared__ int s_tot;
    if (lane == 31) s_wsum[warp] = ip;
    __syncthreads();
    if (t == 0) {
        int a = 0;
#pragma unroll
        for (int w = 0; w < 8; w++) { s_woff[w] = a; a += s_wsum[w]; }
        s_tot = a;
    }
    __syncthreads();

    int tail = *tail_p;
    int ws = tail % Q; if (ws < 0) ws += Q;

    int offp = ip - lp + s_woff[warp];     // exclusive rank
#pragma unroll
    for (int k = 0; k < CHUNK; k++) {
        if ((mask >> k) & 1u) {
            int pos = ws + offp;
            if (pos >= Q) pos -= Q;
            g_pos[base + k] = pos;
            offp++;
        }
    }

    if (t == 0) {
        g_wstart = ws;
        g_wlen   = s_tot;
        g_done   = 0;                      // self-reset for next call
    }
}

// ---------------------------------------------------------------------------
// 2) Mean + copy. Blocks [0, COPYB): grid-stride window-skip copy of
//    queue+labels (streaming loads/stores — L2-neutral). Blocks
//    [COPYB, COPYB+NC): one class each — R10's proven shape: 64 threads,
//    thread t owns float4 column t, 8-row unroll, DEFAULT-cached feature
//    loads (L2-resident across graph replays), streaming output stores.
// ---------------------------------------------------------------------------
__global__ void __launch_bounds__(64) mean_copy_kernel(
        const float4* __restrict__ feat,
        const int* __restrict__ labels, int N,
        const float4* __restrict__ queue_in,
        const float* __restrict__ label_in,
        float* __restrict__ out, int Q) {
    int t = threadIdx.x;

    if (blockIdx.x < COPYB) {
        // ---- copy role (leading blocks: co-run with the mean wave) ----
        int ws = g_wstart, wl = g_wlen;
        int nq4 = Q * NV4;
        int total = nq4 + Q;
        int stride = COPYB * 64;
        for (int i = blockIdx.x * 64 + t; i < total; i += stride) {
            if (i < nq4) {
                int row = i >> 6;                 // NV4 = 64
                int d = row - ws; if (d < 0) d += Q;
                if (d >= wl) __stcs((float4*)out + i, __ldcs(queue_in + i));
            } else {
                int j = i - nq4;
                int d = j - ws; if (d < 0) d += Q;
                if (d >= wl)
                    __stcs(out + (size_t)Q * FEAT + j, __ldcs(label_in + j));
            }
        }
        return;
    }

    // ---- mean role ----
    __shared__ int sidx[CAP];
    int c = blockIdx.x - COPYB;

    int4 cv = g_cnt4[c];                     // fresh launch: L1 was flushed
    int cnt = cv.x + cv.y + cv.z + cv.w;
    if (cnt == 0) return;                    // uniform

    int pos = g_pos[c];
    float4 acc = make_float4(0.f, 0.f, 0.f, 0.f);
    bool ovf = (cv.x > RCAP) | (cv.y > RCAP) | (cv.z > RCAP) | (cv.w > RCAP);

    if (!ovf) {
        // compact the 4 replica segments into smem (cnt <= 128)
        int cr[4] = {cv.x, cv.y, cv.z, cv.w};
        int off = 0;
#pragma unroll
        for (int r = 0; r < 4; r++) {
            if (t < cr[r]) sidx[off + t] = g_bucket[c * CAP + r * RCAP + t];
            off += cr[r];
        }
        __syncthreads();                     // orders count reads AND sidx
        if (t == 0) g_cnt4[c] = make_int4(0, 0, 0, 0);   // reset after barrier

        int r = 0;
        for (; r + 8 <= cnt; r += 8) {
            float4 v0 = feat[(size_t)sidx[r + 0] * NV4 + t];
            float4 v1 = feat[(size_t)sidx[r + 1] * NV4 + t];
            float4 v2 = feat[(size_t)sidx[r + 2] * NV4 + t];
            float4 v3 = feat[(size_t)sidx[r + 3] * NV4 + t];
            float4 v4 = feat[(size_t)sidx[r + 4] * NV4 + t];
            float4 v5 = feat[(size_t)sidx[r + 5] * NV4 + t];
            float4 v6 = feat[(size_t)sidx[r + 6] * NV4 + t];
            float4 v7 = feat[(size_t)sidx[r + 7] * NV4 + t];
            acc.x += (v0.x + v1.x) + (v2.x + v3.x) + (v4.x + v5.x) + (v6.x + v7.x);
            acc.y += (v0.y + v1.y) + (v2.y + v3.y) + (v4.y + v5.y) + (v6.y + v7.y);
            acc.z += (v0.z + v1.z) + (v2.z + v3.z) + (v4.z + v5.z) + (v6.z + v7.z);
            acc.w += (v0.w + v1.w) + (v2.w + v3.w) + (v4.w + v5.w) + (v6.w + v7.w);
        }
        for (; r < cnt; r++) {
            float4 v = feat[(size_t)sidx[r] * NV4 + t];
            acc.x += v.x; acc.y += v.y; acc.z += v.z; acc.w += v.w;
        }
    } else {
        // Generic fallback: rescan all labels (correct for any input).
        __syncthreads();
        if (t == 0) g_cnt4[c] = make_int4(0, 0, 0, 0);
        for (int i = 0; i < N; i++) {
            if (__ldg(&labels[i]) == c) {
                float4 v = feat[(size_t)i * NV4 + t];
                acc.x += v.x; acc.y += v.y; acc.z += v.z; acc.w += v.w;
            }
        }
    }

    float inv = 1.0f / (float)cnt;
    float4 o = make_float4(acc.x * inv, acc.y * inv, acc.z * inv, acc.w * inv);
    __stcs((float4*)out + (size_t)pos * NV4 + t, o);
    if (t == 0) out[(size_t)Q * FEAT + pos] = (float)c;
}

// ---------------------------------------------------------------------------
// Launch.  Inputs: features f32[N,256], pid_labels i32[N],
//   large_batch_queue f32[Q,256], queue_label f32[Q], tail i32[1]
// Output: [new_queue f32[Q,256] | new_label f32[Q]]
// ---------------------------------------------------------------------------
extern "C" void kernel_launch(void* const* d_in, const int* in_sizes, int n_in,
                              void* d_out, int out_size) {
    const float4* feat    = (const float4*)d_in[0];
    const int*    labels  = (const int*)d_in[1];
    const float4* queue0  = (const float4*)d_in[2];
    const float*  qlabel0 = (const float*)d_in[3];
    const int*    tail_p  = (const int*)d_in[4];

    int N = in_sizes[1];              // 131072
    int Q = in_sizes[3];              // 11064
    float* out = (float*)d_out;

    // 1) tickets + last-block scan (one launch)
    {
        int threads = 256;
        int blocks = (N + threads - 1) / threads;   // 512
        bucket_scan_kernel<<<blocks, threads>>>(labels, N, tail_p, Q);
    }
    // 2) leading window-skip copy + per-class gather/mean/scatter
    mean_copy_kernel<<<COPYB + NC, 64>>>(feat, labels, N,
                                         queue0, qlabel0, out, Q);
}